// round 5
// baseline (speedup 1.0000x reference)
#include <cuda_runtime.h>

#define B_ 64
#define S_ 512
#define I_ 256
#define O_ 256

// Scratch: xg[m][n], m = s*64 + b (32768), n = gate*256 + o (1024). 134 MB.
__device__ float g_xg[(size_t)S_ * B_ * 4 * O_];
// Flags: g_flags[s*4 + bg] counts hidden-group CTAs done writing h for step s.
__device__ int g_flags[S_ * 4];

// ---------------------------------------------------------------------------
// helpers
// ---------------------------------------------------------------------------
__device__ __forceinline__ unsigned long long ffma2(unsigned long long a,
                                                    unsigned long long b,
                                                    unsigned long long c) {
    unsigned long long d;
    asm("fma.rn.f32x2 %0, %1, %2, %3;" : "=l"(d) : "l"(a), "l"(b), "l"(c));
    return d;
}
__device__ __forceinline__ float f2lo(unsigned long long v) {
    return __uint_as_float((unsigned)v);
}
__device__ __forceinline__ float f2hi(unsigned long long v) {
    return __uint_as_float((unsigned)(v >> 32));
}
__device__ __forceinline__ float sigf(float x) {
    return 1.0f / (1.0f + __expf(-x));
}
__device__ __forceinline__ float tanhx(float x) {
    return 2.0f * sigf(2.0f * x) - 1.0f;
}

// ---------------------------------------------------------------------------
// Phase 1: xg[m][n] = sum_i x[b,s,i] * Wx[n,i] + bx[n] + bh[n]
//   M=32768 (m=s*64+b), N=1024, K=256. Both operands K-contiguous.
//   BM=128, BN=64, BK=16, 256 threads, 8x4 register tile, f32x2 k-pair FMAs.
// ---------------------------------------------------------------------------
__global__ void __launch_bounds__(256) gemm_xg_kernel(
    const float* __restrict__ x, const float* __restrict__ Wx,
    const float* __restrict__ bx, const float* __restrict__ bh) {
    __shared__ __align__(16) float As[128][20];  // [row][k], padded
    __shared__ __align__(16) float Bs[64][20];

    const int t  = threadIdx.x;
    const int bn = blockIdx.x;   // 0..15
    const int bm = blockIdx.y;   // 0..255
    const int tx = t & 15;       // owns columns tx + j*16
    const int ty = t >> 4;       // owns rows    ty + i*16

    const int arow = t & 127;
    const int akv  = (t >> 7) * 8;         // 0 or 8
    const int m_l  = bm * 128 + arow;      // global m
    const float* arp = x + ((size_t)(m_l & 63) * S_ + (m_l >> 6)) * I_;
    const int brow = t & 63;
    const int bk   = (t >> 6) * 4;         // 0,4,8,12
    const float* brp = Wx + (size_t)(bn * 64 + brow) * I_;

    unsigned long long acc[8][4];
#pragma unroll
    for (int i = 0; i < 8; ++i)
#pragma unroll
        for (int j = 0; j < 4; ++j) acc[i][j] = 0ULL;

    for (int kt = 0; kt < I_; kt += 16) {
        float4 a0 = *(const float4*)(arp + kt + akv);
        float4 a1 = *(const float4*)(arp + kt + akv + 4);
        float4 bv = *(const float4*)(brp + kt + bk);
        __syncthreads();
        *(float4*)&As[arow][akv]     = a0;
        *(float4*)&As[arow][akv + 4] = a1;
        *(float4*)&Bs[brow][bk]      = bv;
        __syncthreads();
#pragma unroll
        for (int k4 = 0; k4 < 4; ++k4) {
            ulonglong2 a2[8], b2[4];
#pragma unroll
            for (int i = 0; i < 8; ++i)
                a2[i] = *(const ulonglong2*)&As[ty + i * 16][k4 * 4];
#pragma unroll
            for (int j = 0; j < 4; ++j)
                b2[j] = *(const ulonglong2*)&Bs[tx + j * 16][k4 * 4];
#pragma unroll
            for (int i = 0; i < 8; ++i)
#pragma unroll
                for (int j = 0; j < 4; ++j) {
                    acc[i][j] = ffma2(a2[i].x, b2[j].x, acc[i][j]);
                    acc[i][j] = ffma2(a2[i].y, b2[j].y, acc[i][j]);
                }
        }
    }

#pragma unroll
    for (int j = 0; j < 4; ++j) {
        const int n = bn * 64 + tx + j * 16;
        const float bias = bx[n] + bh[n];
#pragma unroll
        for (int i = 0; i < 8; ++i) {
            const int m = bm * 128 + ty + i * 16;
            g_xg[(size_t)m * 1024 + n] = f2lo(acc[i][j]) + f2hi(acc[i][j]) + bias;
        }
    }
}

// ---------------------------------------------------------------------------
// flag reset (graph-replay safe: runs before every recurrence launch)
// ---------------------------------------------------------------------------
__global__ void reset_flags_kernel() {
    int i = blockIdx.x * blockDim.x + threadIdx.x;
    if (i < S_ * 4) g_flags[i] = 0;
}

// ---------------------------------------------------------------------------
// Phase 2: persistent recurrence.
//   128 CTAs = 4 batch-groups (16 b) x 32 hidden-groups (8 o).
//   128 threads = 4 warps (k-slices of 64) x 32 lanes (gate-rows gate*8+oh).
//   Wh slice in registers, h staged in smem (broadcast reads), c in regs.
//   Cross-CTA handoff: h written to h_seq (output), flag per (s, bg).
// ---------------------------------------------------------------------------
__global__ void __launch_bounds__(128, 1) lstm_rec_kernel(
    const float* __restrict__ h0, const float* __restrict__ c0,
    const float* __restrict__ Wh, float* __restrict__ out) {
    __shared__ __align__(16) float h_s[16][260];  // [b_local][k], padded
    __shared__ float red[4][32][17];              // [warp][gate-row][b]
    __shared__ float g_s[32][17];                 // [gate-row][b]

    const int t  = threadIdx.x;
    const int bg = blockIdx.x >> 5;  // 0..3
    const int og = blockIdx.x & 31;  // 0..31
    const int w  = t >> 5;           // warp = k-slice
    const int l  = t & 31;           // lane = gate-row

    // recurrent weights -> registers (as f32x2 pairs)
    unsigned long long wp[32];
    {
        const int gate = l >> 3, oh = l & 7;
        const int grow = gate * 256 + og * 8 + oh;
        const unsigned long long* wr =
            (const unsigned long long*)(Wh + (size_t)grow * 256 + w * 64);
#pragma unroll
        for (int j = 0; j < 32; ++j) wp[j] = wr[j];
    }

    // per-thread state-update assignment: one (oh, b) pair
    const int oh_u = t & 7;
    const int b_u  = t >> 3;  // 0..15
    const int o_g  = og * 8 + oh_u;
    const int b_g  = bg * 16 + b_u;
    float creg = c0[(size_t)b_g * 256 + o_g];

    // fill mapping: thread loads 32 floats of h for one local batch
    const int b_l = t & 15;
    const int kq  = t >> 4;  // 0..7

    float* hT = out + (size_t)B_ * S_ * O_;
    float* cT = hT + (size_t)B_ * O_;

    for (int s = 0; s < S_; ++s) {
        // acquire previous step's h (written by the 32 CTAs of this bg)
        if (s > 0) {
            if (t == 0) {
                volatile int* f = &g_flags[(s - 1) * 4 + bg];
                while (*f < 32) {}
                __threadfence();
            }
            __syncthreads();
        }

        // stage h into smem; bypass L1 (freshly written on other SMs)
        {
            const float* src = (s == 0)
                ? (h0 + (size_t)(bg * 16 + b_l) * 256 + kq * 32)
                : (out + ((size_t)(bg * 16 + b_l) * S_ + (s - 1)) * 256 + kq * 32);
            float4* dst = (float4*)&h_s[b_l][kq * 32];
#pragma unroll
            for (int j = 0; j < 8; ++j) dst[j] = __ldcg((const float4*)src + j);
        }

        // prefetch this step's input-side gate contributions
        float xgv[4];
        {
            const float* xp = g_xg + (size_t)(s * 64 + b_g) * 1024 + o_g;
#pragma unroll
            for (int g = 0; g < 4; ++g) xgv[g] = xp[g * 256];
        }
        __syncthreads();

        // dot: acc[b] = sum over this warp's 64-k slice of h[b][k]*w[k]
        unsigned long long acc[16];
#pragma unroll
        for (int b = 0; b < 16; ++b) acc[b] = 0ULL;
        const float* hbase = &h_s[0][w * 64];
#pragma unroll 4
        for (int k4 = 0; k4 < 16; ++k4) {
            const unsigned long long w2a = wp[2 * k4];
            const unsigned long long w2b = wp[2 * k4 + 1];
#pragma unroll
            for (int b = 0; b < 16; ++b) {
                ulonglong2 h2 = *(const ulonglong2*)(hbase + (size_t)b * 260 + k4 * 4);
                acc[b] = ffma2(h2.x, w2a, acc[b]);
                acc[b] = ffma2(h2.y, w2b, acc[b]);
            }
        }
#pragma unroll
        for (int b = 0; b < 16; ++b)
            red[w][l][b] = f2lo(acc[b]) + f2hi(acc[b]);
        __syncthreads();

        // cross-warp k-slice reduction
        {
            const int r  = t >> 2;
            const int b0 = (t & 3) * 4;
#pragma unroll
            for (int q = 0; q < 4; ++q) {
                const int b = b0 + q;
                g_s[r][b] = red[0][r][b] + red[1][r][b] + red[2][r][b] + red[3][r][b];
            }
        }
        __syncthreads();

        // gates + state update + publish h
        {
            const float gf = g_s[oh_u][b_u]      + xgv[0];
            const float gi = g_s[8 + oh_u][b_u]  + xgv[1];
            const float gc = g_s[16 + oh_u][b_u] + xgv[2];
            const float go = g_s[24 + oh_u][b_u] + xgv[3];
            const float fg  = sigf(gf);
            const float ig  = sigf(gi);
            const float cg  = tanhx(gc);
            const float ogt = sigf(go);
            creg = creg * fg + ig * cg;
            const float hv = ogt * tanhx(creg);
            out[((size_t)b_g * S_ + s) * 256 + o_g] = hv;
            if (s == S_ - 1) {
                hT[(size_t)b_g * 256 + o_g] = hv;
                cT[(size_t)b_g * 256 + o_g] = creg;
            }
        }
        __threadfence();
        __syncthreads();
        if (t == 0) atomicAdd(&g_flags[s * 4 + bg], 1);
    }
}

// ---------------------------------------------------------------------------
// launch
// ---------------------------------------------------------------------------
extern "C" void kernel_launch(void* const* d_in, const int* in_sizes, int n_in,
                              void* d_out, int out_size) {
    (void)in_sizes; (void)n_in; (void)out_size;
    const float* x  = (const float*)d_in[0];
    const float* h0 = (const float*)d_in[1];
    const float* c0 = (const float*)d_in[2];
    const float* Wh = (const float*)d_in[3];
    const float* bh = (const float*)d_in[4];
    const float* Wx = (const float*)d_in[5];
    const float* bx = (const float*)d_in[6];
    float* out = (float*)d_out;

    dim3 g1(1024 / 64, (S_ * B_) / 128);  // (16, 256)
    gemm_xg_kernel<<<g1, 256>>>(x, Wx, bx, bh);
    reset_flags_kernel<<<8, 256>>>();
    lstm_rec_kernel<<<128, 128>>>(h0, c0, Wh, out);
}

// round 6
// speedup vs baseline: 1.2417x; 1.2417x over previous
#include <cuda_runtime.h>

#define B_ 64
#define S_ 512
#define I_ 256
#define O_ 256

// Scratch: xg[m][n], m = s*64 + b (32768), n = gate*256 + o (1024). 134 MB.
__device__ float g_xg[(size_t)S_ * B_ * 4 * O_];

// ---------------------------------------------------------------------------
// helpers
// ---------------------------------------------------------------------------
__device__ __forceinline__ unsigned long long ffma2(unsigned long long a,
                                                    unsigned long long b,
                                                    unsigned long long c) {
    unsigned long long d;
    asm("fma.rn.f32x2 %0, %1, %2, %3;" : "=l"(d) : "l"(a), "l"(b), "l"(c));
    return d;
}
__device__ __forceinline__ float f2lo(unsigned long long v) {
    return __uint_as_float((unsigned)v);
}
__device__ __forceinline__ float f2hi(unsigned long long v) {
    return __uint_as_float((unsigned)(v >> 32));
}
__device__ __forceinline__ float sigf(float x) {
    return 1.0f / (1.0f + __expf(-x));
}
__device__ __forceinline__ float tanhx(float x) {
    return 2.0f * sigf(2.0f * x) - 1.0f;
}
__device__ __forceinline__ unsigned smem_u32(const void* p) {
    return (unsigned)__cvta_generic_to_shared(p);
}
// push one float into the same smem offset of cluster CTA `rank`
__device__ __forceinline__ void dsmem_st_f32(unsigned local_addr, int rank, float v) {
    unsigned ra;
    asm volatile("mapa.shared::cluster.u32 %0, %1, %2;"
                 : "=r"(ra) : "r"(local_addr), "r"(rank));
    asm volatile("st.shared::cluster.f32 [%0], %1;" :: "r"(ra), "f"(v) : "memory");
}

// ---------------------------------------------------------------------------
// Phase 1: xg[m][n] = sum_i x[b,s,i] * Wx[n,i] + bx[n] + bh[n]
//   M=32768 (m=s*64+b), N=1024, K=256. BM=BN=128, BK=16, 256 thr, 8x8 tile.
// ---------------------------------------------------------------------------
__global__ void __launch_bounds__(256, 1) gemm_xg_kernel(
    const float* __restrict__ x, const float* __restrict__ Wx,
    const float* __restrict__ bx, const float* __restrict__ bh) {
    __shared__ __align__(16) float As[128][20];
    __shared__ __align__(16) float Bs[128][20];

    const int t  = threadIdx.x;
    const int bn = blockIdx.x;   // 0..7
    const int bm = blockIdx.y;   // 0..255
    const int tx = t & 15;       // cols tx + j*16
    const int ty = t >> 4;       // rows ty + i*16

    const int arow  = t & 127;
    const int ahalf = (t >> 7) * 8;            // 0 or 8
    const int m_l   = bm * 128 + arow;
    const float* arp = x + ((size_t)(m_l & 63) * S_ + (m_l >> 6)) * I_ + ahalf;
    const int brow  = t & 127;
    const int bhalf = (t >> 7) * 8;
    const float* brp = Wx + (size_t)(bn * 128 + brow) * I_ + bhalf;

    unsigned long long acc[8][8];
#pragma unroll
    for (int i = 0; i < 8; ++i)
#pragma unroll
        for (int j = 0; j < 8; ++j) acc[i][j] = 0ULL;

    // prefetch tile 0
    float4 pa0 = *(const float4*)(arp + 0);
    float4 pa1 = *(const float4*)(arp + 4);
    float4 pb0 = *(const float4*)(brp + 0);
    float4 pb1 = *(const float4*)(brp + 4);

    for (int kt = 0; kt < I_; kt += 16) {
        __syncthreads();
        *(float4*)&As[arow][ahalf]     = pa0;
        *(float4*)&As[arow][ahalf + 4] = pa1;
        *(float4*)&Bs[brow][bhalf]     = pb0;
        *(float4*)&Bs[brow][bhalf + 4] = pb1;
        __syncthreads();
        if (kt + 16 < I_) {
            pa0 = *(const float4*)(arp + kt + 16);
            pa1 = *(const float4*)(arp + kt + 20);
            pb0 = *(const float4*)(brp + kt + 16);
            pb1 = *(const float4*)(brp + kt + 20);
        }
#pragma unroll
        for (int k4 = 0; k4 < 4; ++k4) {
            ulonglong2 a2[8];
#pragma unroll
            for (int i = 0; i < 8; ++i)
                a2[i] = *(const ulonglong2*)&As[ty + i * 16][k4 * 4];
#pragma unroll
            for (int j = 0; j < 8; ++j) {
                ulonglong2 b2 = *(const ulonglong2*)&Bs[tx + j * 16][k4 * 4];
#pragma unroll
                for (int i = 0; i < 8; ++i) {
                    acc[i][j] = ffma2(a2[i].x, b2.x, acc[i][j]);
                    acc[i][j] = ffma2(a2[i].y, b2.y, acc[i][j]);
                }
            }
        }
    }

#pragma unroll
    for (int j = 0; j < 8; ++j) {
        const int n = bn * 128 + tx + j * 16;
        const float bias = bx[n] + bh[n];
#pragma unroll
        for (int i = 0; i < 8; ++i) {
            const int m = bm * 128 + ty + i * 16;
            g_xg[(size_t)m * 1024 + n] = f2lo(acc[i][j]) + f2hi(acc[i][j]) + bias;
        }
    }
}

// ---------------------------------------------------------------------------
// Phase 2: clustered persistent recurrence.
//   16 clusters x 8 CTAs. Cluster cid owns batches [cid*4, cid*4+4).
//   CTA rank r owns o in [r*32, r*32+32). 256 threads = 8 warps (k-slices
//   of 32) x 32 lanes (o-offset). Lane holds Wh for 4 gates x 32 k in regs.
//   h double-buffered in smem; handoff = DSMEM push + barrier.cluster.
// ---------------------------------------------------------------------------
__global__ void __cluster_dims__(8, 1, 1) __launch_bounds__(256, 1)
lstm_rec_kernel(const float* __restrict__ h0, const float* __restrict__ c0,
                const float* __restrict__ Wh, float* __restrict__ out) {
    __shared__ __align__(16) float h_s[2][4][256];  // [parity][b][o]
    __shared__ float red[8][512];                   // [warp][(b*4+g)*32+oo]
    __shared__ float gsum[512];

    const int t   = threadIdx.x;
    const int cid = blockIdx.x >> 3;  // 0..15
    const int r   = blockIdx.x & 7;   // 0..7
    const int w   = t >> 5;           // k-slice
    const int l   = t & 31;           // o-offset

    // recurrent weights -> registers: wp[g][k2] covers k = w*32 + k2*2 (+1)
    unsigned long long wp[4][16];
#pragma unroll
    for (int g = 0; g < 4; ++g) {
        const float* wr = Wh + ((size_t)(g * 256 + r * 32 + l) * 256 + w * 32);
#pragma unroll
        for (int k2 = 0; k2 < 16; ++k2)
            wp[g][k2] = *(const unsigned long long*)(wr + k2 * 2);
    }

    // cell-update mapping: thread t<128 owns (b = t>>5, oo = t&31)
    const bool cell = (t < 128);
    const int cb = (t >> 5) & 3;
    const int co = t & 31;
    const int b_g = cid * 4 + cb;           // global batch
    const int o_g = r * 32 + co;            // global hidden index
    float creg = cell ? c0[(size_t)b_g * 256 + o_g] : 0.0f;

    // stage h0 into buffer 0 (each CTA loads all 4x256)
    {
        const int b_l = t >> 6;
        const int off = (t & 63) * 4;
        *(float4*)&h_s[0][b_l][off] =
            *(const float4*)(h0 + (size_t)(cid * 4 + b_l) * 256 + off);
    }
    __syncthreads();

    // prefetch xg for s=0
    float xgv[4];
    if (cell) {
        const float* xp = g_xg + (size_t)(0 * 64 + b_g) * 1024 + o_g;
#pragma unroll
        for (int g = 0; g < 4; ++g) xgv[g] = __ldcg(xp + g * 256);
    }

    float* hT = out + (size_t)B_ * S_ * O_;
    float* cT = hT + (size_t)B_ * O_;
    const unsigned hbuf_a[2] = {smem_u32(&h_s[0][0][0]), smem_u32(&h_s[1][0][0])};

    int p = 0;
    for (int s = 0; s < S_; ++s, p ^= 1) {
        if (s > 0) asm volatile("barrier.cluster.wait.aligned;" ::: "memory");

        // dot: acc[b][g] over this warp's 32-k slice (f32x2 pairs)
        unsigned long long acc[4][4];
#pragma unroll
        for (int b = 0; b < 4; ++b)
#pragma unroll
            for (int g = 0; g < 4; ++g) acc[b][g] = 0ULL;
#pragma unroll
        for (int b = 0; b < 4; ++b) {
            const unsigned long long* hb =
                (const unsigned long long*)&h_s[p][b][w * 32];
#pragma unroll
            for (int k2 = 0; k2 < 16; ++k2) {
                const unsigned long long h2 = hb[k2];
                acc[b][0] = ffma2(h2, wp[0][k2], acc[b][0]);
                acc[b][1] = ffma2(h2, wp[1][k2], acc[b][1]);
                acc[b][2] = ffma2(h2, wp[2][k2], acc[b][2]);
                acc[b][3] = ffma2(h2, wp[3][k2], acc[b][3]);
            }
        }
#pragma unroll
        for (int b = 0; b < 4; ++b)
#pragma unroll
            for (int g = 0; g < 4; ++g)
                red[w][(b * 4 + g) * 32 + l] = f2lo(acc[b][g]) + f2hi(acc[b][g]);
        __syncthreads();

        // cross-warp reduction: thread t sums entries t and t+256
        {
            float s0 = 0.0f, s1 = 0.0f;
#pragma unroll
            for (int w2 = 0; w2 < 8; ++w2) {
                s0 += red[w2][t];
                s1 += red[w2][t + 256];
            }
            gsum[t] = s0;
            gsum[t + 256] = s1;
        }
        __syncthreads();

        // gates + state update + publish
        if (cell) {
            const float gf = gsum[(cb * 4 + 0) * 32 + co] + xgv[0];
            const float gi = gsum[(cb * 4 + 1) * 32 + co] + xgv[1];
            const float gc = gsum[(cb * 4 + 2) * 32 + co] + xgv[2];
            const float go = gsum[(cb * 4 + 3) * 32 + co] + xgv[3];
            const float fg  = sigf(gf);
            const float ig  = sigf(gi);
            const float cg  = tanhx(gc);
            const float ogt = sigf(go);
            creg = creg * fg + ig * cg;
            const float hv = ogt * tanhx(creg);
            out[((size_t)b_g * S_ + s) * 256 + o_g] = hv;
            if (s == S_ - 1) {
                hT[(size_t)b_g * 256 + o_g] = hv;
                cT[(size_t)b_g * 256 + o_g] = creg;
            } else {
                // push hv into every cluster CTA's next-parity buffer
                const unsigned dst = hbuf_a[p ^ 1] + (unsigned)(cb * 256 + o_g) * 4u;
#pragma unroll
                for (int rk = 0; rk < 8; ++rk) dsmem_st_f32(dst, rk, hv);
            }
        }
        if (s < S_ - 1) {
            asm volatile("barrier.cluster.arrive.aligned;" ::: "memory");
            // prefetch next step's xg while peers arrive
            if (cell) {
                const float* xp = g_xg + (size_t)((s + 1) * 64 + b_g) * 1024 + o_g;
#pragma unroll
                for (int g = 0; g < 4; ++g) xgv[g] = __ldcg(xp + g * 256);
            }
        }
    }
}

// ---------------------------------------------------------------------------
// launch
// ---------------------------------------------------------------------------
extern "C" void kernel_launch(void* const* d_in, const int* in_sizes, int n_in,
                              void* d_out, int out_size) {
    (void)in_sizes; (void)n_in; (void)out_size;
    const float* x  = (const float*)d_in[0];
    const float* h0 = (const float*)d_in[1];
    const float* c0 = (const float*)d_in[2];
    const float* Wh = (const float*)d_in[3];
    const float* bh = (const float*)d_in[4];
    const float* Wx = (const float*)d_in[5];
    const float* bx = (const float*)d_in[6];
    float* out = (float*)d_out;

    dim3 g1(1024 / 128, (S_ * B_) / 128);  // (8, 256)
    gemm_xg_kernel<<<g1, 256>>>(x, Wx, bx, bh);
    lstm_rec_kernel<<<128, 256>>>(h0, c0, Wh, out);
}

// round 7
// speedup vs baseline: 1.6743x; 1.3484x over previous
#include <cuda_runtime.h>

#define B_ 64
#define S_ 512
#define I_ 256
#define O_ 256

typedef unsigned long long ULL;

// Scratch: xg[m][n], m = s*64 + b (32768), n = gate*256 + o (1024). 134 MB.
__device__ float g_xg[(size_t)S_ * B_ * 4 * O_];

// ---------------------------------------------------------------------------
// helpers
// ---------------------------------------------------------------------------
__device__ __forceinline__ ULL ffma2(ULL a, ULL b, ULL c) {
    ULL d;
    asm("fma.rn.f32x2 %0, %1, %2, %3;" : "=l"(d) : "l"(a), "l"(b), "l"(c));
    return d;
}
__device__ __forceinline__ float f2lo(ULL v) { return __uint_as_float((unsigned)v); }
__device__ __forceinline__ float f2hi(ULL v) { return __uint_as_float((unsigned)(v >> 32)); }
__device__ __forceinline__ float sigf(float x) { return 1.0f / (1.0f + __expf(-x)); }
__device__ __forceinline__ float tanhx(float x) { return 2.0f * sigf(2.0f * x) - 1.0f; }
__device__ __forceinline__ unsigned smem_u32(const void* p) {
    return (unsigned)__cvta_generic_to_shared(p);
}
__device__ __forceinline__ unsigned my_ctarank() {
    unsigned r; asm("mov.u32 %0, %%cluster_ctarank;" : "=r"(r)); return r;
}
__device__ __forceinline__ void dsmem_st_f32(unsigned local_addr, int rank, float v) {
    unsigned ra;
    asm volatile("mapa.shared::cluster.u32 %0, %1, %2;"
                 : "=r"(ra) : "r"(local_addr), "r"(rank));
    asm volatile("st.shared::cluster.f32 [%0], %1;" :: "r"(ra), "f"(v) : "memory");
}
__device__ __forceinline__ void mbar_arrive_rank(unsigned local_mbar, int rank) {
    asm volatile(
        "{\n\t.reg .b32 ra;\n\t"
        "mapa.shared::cluster.u32 ra, %0, %1;\n\t"
        "mbarrier.arrive.release.cluster.shared::cluster.b64 _, [ra];\n\t}"
        :: "r"(local_mbar), "r"(rank) : "memory");
}
__device__ __forceinline__ void mbar_wait_cluster(unsigned mbar, unsigned parity) {
    asm volatile(
        "{\n\t.reg .pred P1;\n\t"
        "WAIT_%=:\n\t"
        "mbarrier.try_wait.parity.acquire.cluster.shared::cta.b64 P1, [%0], %1, 0x989680;\n\t"
        "@P1 bra.uni DONE_%=;\n\t"
        "bra.uni WAIT_%=;\n\t"
        "DONE_%=:\n\t}"
        :: "r"(mbar), "r"(parity) : "memory");
}

// ---------------------------------------------------------------------------
// Phase 1: xg[m][n] = sum_i x[b,s,i] * Wx[n,i] + bx[n] + bh[n]
//   M=32768 (m=s*64+b), N=1024, K=256. BM=BN=128, BK=16, 256 thr, 8x8 tile.
// ---------------------------------------------------------------------------
__global__ void __launch_bounds__(256, 1) gemm_xg_kernel(
    const float* __restrict__ x, const float* __restrict__ Wx,
    const float* __restrict__ bx, const float* __restrict__ bh) {
    __shared__ __align__(16) float As[128][20];
    __shared__ __align__(16) float Bs[128][20];

    const int t  = threadIdx.x;
    const int bn = blockIdx.x;   // 0..7
    const int bm = blockIdx.y;   // 0..255
    const int tx = t & 15;
    const int ty = t >> 4;

    const int arow  = t & 127;
    const int ahalf = (t >> 7) * 8;            // 0 or 8
    const int m_l   = bm * 128 + arow;
    const float* arp = x + ((size_t)(m_l & 63) * S_ + (m_l >> 6)) * I_ + ahalf;
    const int brow  = t & 127;
    const int bhalf = (t >> 7) * 8;
    const float* brp = Wx + (size_t)(bn * 128 + brow) * I_ + bhalf;

    ULL acc[8][8];
#pragma unroll
    for (int i = 0; i < 8; ++i)
#pragma unroll
        for (int j = 0; j < 8; ++j) acc[i][j] = 0ULL;

    float4 pa0 = *(const float4*)(arp + 0);
    float4 pa1 = *(const float4*)(arp + 4);
    float4 pb0 = *(const float4*)(brp + 0);
    float4 pb1 = *(const float4*)(brp + 4);

    for (int kt = 0; kt < I_; kt += 16) {
        __syncthreads();
        *(float4*)&As[arow][ahalf]     = pa0;
        *(float4*)&As[arow][ahalf + 4] = pa1;
        *(float4*)&Bs[brow][bhalf]     = pb0;
        *(float4*)&Bs[brow][bhalf + 4] = pb1;
        __syncthreads();
        if (kt + 16 < I_) {
            pa0 = *(const float4*)(arp + kt + 16);
            pa1 = *(const float4*)(arp + kt + 20);
            pb0 = *(const float4*)(brp + kt + 16);
            pb1 = *(const float4*)(brp + kt + 20);
        }
#pragma unroll
        for (int k4 = 0; k4 < 4; ++k4) {
            ulonglong2 a2[8];
#pragma unroll
            for (int i = 0; i < 8; ++i)
                a2[i] = *(const ulonglong2*)&As[ty + i * 16][k4 * 4];
#pragma unroll
            for (int j = 0; j < 8; ++j) {
                ulonglong2 b2 = *(const ulonglong2*)&Bs[tx + j * 16][k4 * 4];
#pragma unroll
                for (int i = 0; i < 8; ++i) {
                    acc[i][j] = ffma2(a2[i].x, b2.x, acc[i][j]);
                    acc[i][j] = ffma2(a2[i].y, b2.y, acc[i][j]);
                }
            }
        }
    }

#pragma unroll
    for (int j = 0; j < 8; ++j) {
        const int n = bn * 128 + tx + j * 16;
        const float bias = bx[n] + bh[n];
#pragma unroll
        for (int i = 0; i < 8; ++i) {
            const int m = bm * 128 + ty + i * 16;
            g_xg[(size_t)m * 1024 + n] = f2lo(acc[i][j]) + f2hi(acc[i][j]) + bias;
        }
    }
}

// ---------------------------------------------------------------------------
// Phase 2: 32 clusters x 4 CTAs; cluster owns 2 batches; CTA rank r owns
//   o in [r*64, r*64+64). 256 threads; thread t owns gate-row t
//   (g = t>>6, o = r*64 + (t&63)) for BOTH batches, full k=256:
//   k[0,128) in registers (64 ULL pairs), k[128,256) in smem.
//   No cross-warp reduction. Handoff: 512B DSMEM push + mbarrier per step.
// ---------------------------------------------------------------------------
// dynamic smem layout (bytes):
//   [0, 131072)            ulonglong2 w2[32][256]   (k4-major, row minor)
//   [131072, 135168)       float h_s[2][2][256]     (parity, b, k)
//   [135168, 137216)       float gsm[2][256]        (b, gate-row)
//   [137216, 137232)       ULL mbar[2]
#define SM_W2   0
#define SM_HS   131072
#define SM_GSM  135168
#define SM_MBAR 137216
#define SM_TOTAL 137240

__global__ void __cluster_dims__(4, 1, 1) __launch_bounds__(256, 1)
lstm_rec_kernel(const float* __restrict__ h0, const float* __restrict__ c0,
                const float* __restrict__ Wh, float* __restrict__ out) {
    extern __shared__ __align__(16) unsigned char smraw[];
    ulonglong2* w2 = (ulonglong2*)(smraw + SM_W2);   // [k4][row]
    float* h_sf    = (float*)(smraw + SM_HS);        // [p][b][k]
    float* gsm     = (float*)(smraw + SM_GSM);       // [b][row]
    ULL*   mbar    = (ULL*)(smraw + SM_MBAR);

    const int t   = threadIdx.x;
    const int r   = (int)my_ctarank();     // 0..3
    const int cid = blockIdx.x >> 2;       // 0..31
    const int g   = t >> 6;                // gate of this row
    const int ol  = t & 63;
    const int o_g = r * 64 + ol;           // hidden index of this row

    // ---- weights: row (g, o_g), k[0,128) -> regs; k[128,256) -> smem ----
    const float* wrow = Wh + ((size_t)(g * 256 + o_g)) * 256;
    ULL wpr[64];
#pragma unroll
    for (int k2 = 0; k2 < 64; ++k2) wpr[k2] = *(const ULL*)(wrow + 2 * k2);
#pragma unroll
    for (int k4 = 0; k4 < 32; ++k4)
        w2[k4 * 256 + t] = *(const ulonglong2*)(wrow + 128 + 4 * k4);

    // ---- mbarriers + h0 staging ----
    if (t < 2) {
        unsigned mb = smem_u32(&mbar[t]);
        asm volatile("mbarrier.init.shared.b64 [%0], %1;" :: "r"(mb), "r"(4u) : "memory");
    }
    if (t < 128) {
        const int b = t >> 6, off = (t & 63) * 4;
        *(float4*)&h_sf[b * 256 + off] =
            *(const float4*)(h0 + (size_t)(cid * 2 + b) * 256 + off);
    }
    __syncthreads();
    asm volatile("barrier.cluster.arrive.aligned;" ::: "memory");
    asm volatile("barrier.cluster.wait.aligned;" ::: "memory");

    // ---- cell mapping (threads 0..127): b = t>>6, o = r*64 + (t&63) ----
    const bool cell = (t < 128);
    const int cb  = t >> 6;           // 0/1 (valid when cell)
    const int b_g = cid * 2 + cb;
    float creg = cell ? c0[(size_t)b_g * 256 + o_g] : 0.0f;

    float xgv[4];
    if (cell) {
        const float* xp = g_xg + (size_t)(0 * 64 + b_g) * 1024 + o_g;
#pragma unroll
        for (int gg = 0; gg < 4; ++gg) xgv[gg] = __ldcg(xp + gg * 256);
    }

    float* hT = out + (size_t)B_ * S_ * O_;
    float* cT = hT + (size_t)B_ * O_;
    const unsigned hs_base = smem_u32(h_sf);
    const unsigned mb_a[2] = {smem_u32(&mbar[0]), smem_u32(&mbar[1])};
    unsigned par0 = 0, par1 = 0;

    int p = 0;
    for (int s = 0; s < S_; ++s, p ^= 1) {
        if (s > 0) {
            if (p == 0) { mbar_wait_cluster(mb_a[0], par0); par0 ^= 1; }
            else        { mbar_wait_cluster(mb_a[1], par1); par1 ^= 1; }
        }

        // ---- full-row dot products for both batches ----
        const ULL* hb0 = (const ULL*)&h_sf[(p * 2 + 0) * 256];
        const ULL* hb1 = (const ULL*)&h_sf[(p * 2 + 1) * 256];
        ULL a0 = 0ULL, a1 = 0ULL;
#pragma unroll
        for (int k2 = 0; k2 < 64; ++k2) {
            const ULL h20 = hb0[k2];
            const ULL h21 = hb1[k2];
            a0 = ffma2(h20, wpr[k2], a0);
            a1 = ffma2(h21, wpr[k2], a1);
        }
#pragma unroll 8
        for (int k4 = 0; k4 < 32; ++k4) {
            const ulonglong2 wv = w2[k4 * 256 + t];
            const ULL h00 = hb0[64 + 2 * k4];
            const ULL h01 = hb0[64 + 2 * k4 + 1];
            const ULL h10 = hb1[64 + 2 * k4];
            const ULL h11 = hb1[64 + 2 * k4 + 1];
            a0 = ffma2(h00, wv.x, a0);
            a0 = ffma2(h01, wv.y, a0);
            a1 = ffma2(h10, wv.x, a1);
            a1 = ffma2(h11, wv.y, a1);
        }
        gsm[t]       = f2lo(a0) + f2hi(a0);
        gsm[256 + t] = f2lo(a1) + f2hi(a1);
        __syncthreads();

        // ---- cell update + publish ----
        if (cell) {
            const float* gb = gsm + cb * 256;
            const float gf = gb[ol]       + xgv[0];
            const float gi = gb[64 + ol]  + xgv[1];
            const float gc = gb[128 + ol] + xgv[2];
            const float go = gb[192 + ol] + xgv[3];
            const float fg  = sigf(gf);
            const float ig  = sigf(gi);
            const float cg  = tanhx(gc);
            const float ogt = sigf(go);
            creg = creg * fg + ig * cg;
            const float hv = ogt * tanhx(creg);
            out[((size_t)b_g * S_ + s) * 256 + o_g] = hv;
            if (s == S_ - 1) {
                hT[(size_t)b_g * 256 + o_g] = hv;
                cT[(size_t)b_g * 256 + o_g] = creg;
            } else {
                const unsigned dst =
                    hs_base + (unsigned)(((p ^ 1) * 2 + cb) * 256 + o_g) * 4u;
#pragma unroll
                for (int rk = 0; rk < 4; ++rk) dsmem_st_f32(dst, rk, hv);
            }
        }
        __syncthreads();   // all pushes issued CTA-wide
        if (s < S_ - 1) {
            if (t < 4) mbar_arrive_rank(mb_a[p ^ 1], t);  // cumulative release
            if (cell) {
                const float* xp = g_xg + (size_t)((s + 1) * 64 + b_g) * 1024 + o_g;
#pragma unroll
                for (int gg = 0; gg < 4; ++gg) xgv[gg] = __ldcg(xp + gg * 256);
            }
        }
    }

    asm volatile("barrier.cluster.arrive.aligned;" ::: "memory");
    asm volatile("barrier.cluster.wait.aligned;" ::: "memory");
}

// ---------------------------------------------------------------------------
// launch
// ---------------------------------------------------------------------------
extern "C" void kernel_launch(void* const* d_in, const int* in_sizes, int n_in,
                              void* d_out, int out_size) {
    (void)in_sizes; (void)n_in; (void)out_size;
    const float* x  = (const float*)d_in[0];
    const float* h0 = (const float*)d_in[1];
    const float* c0 = (const float*)d_in[2];
    const float* Wh = (const float*)d_in[3];
    const float* bh = (const float*)d_in[4];
    const float* Wx = (const float*)d_in[5];
    const float* bx = (const float*)d_in[6];
    float* out = (float*)d_out;

    cudaFuncSetAttribute(lstm_rec_kernel,
                         cudaFuncAttributeMaxDynamicSharedMemorySize, SM_TOTAL);

    dim3 g1(1024 / 128, (S_ * B_) / 128);  // (8, 256)
    gemm_xg_kernel<<<g1, 256>>>(x, Wx, bx, bh);
    lstm_rec_kernel<<<128, 256, SM_TOTAL>>>(h0, c0, Wh, out);
}